// round 2
// baseline (speedup 1.0000x reference)
#include <cuda_runtime.h>
#include <cuda_bf16.h>
#include <cstdint>

// Problem: cam (32,4,512,512) f32 -> out[32,4] = mean of top 5243 per row
#define ROWS      128
#define N_PER_ROW (512*512)     // 262144
#define K_SEL     5243
#define SPLIT     4             // CTAs per row in streaming kernel
#define NT1       512
#define NT2       256
#define CAND_CAP  16384
#define NH        1665          // 1664 fine buckets + 1 overflow
#define NHPAD     1792          // NH padded to multiple of NT2
#define LCAP      3072

#define KEY_175   0xBFE00000u   // mono(1.75f)
#define KEY_16    0xC1800000u   // mono(16.0f); (KEY_16-KEY_175)>>14 == 1664

// ---- static device scratch ----
__device__ float    g_cand[(size_t)ROWS * CAND_CAP];
__device__ int      g_cand_cnt[ROWS];
__device__ unsigned g_hcnt[ROWS * NH];
__device__ float    g_hsum[ROWS * NH];

__device__ __forceinline__ unsigned mono(unsigned x) {
    return (x & 0x80000000u) ? ~x : (x | 0x80000000u);
}
__device__ __forceinline__ float unmono(unsigned k) {
    unsigned b = (k & 0x80000000u) ? (k ^ 0x80000000u) : ~k;
    return __uint_as_float(b);
}

// ---- Kernel 0: zero scratch (graph replays re-run this) ----
__global__ void toptk_zero() {
    int idx = blockIdx.x * blockDim.x + threadIdx.x;
    int stride = gridDim.x * blockDim.x;
    for (int i = idx; i < ROWS * NH; i += stride) { g_hcnt[i] = 0u; g_hsum[i] = 0.f; }
    if (idx < ROWS) g_cand_cnt[idx] = 0;
}

// ---- Kernel 1: stream 128MB once. Values >= 1.75: fine 14-bit-granularity
//      smem histogram (counts+sums) + warp-aggregated stash to g_cand. ----
__global__ void __launch_bounds__(NT1) toptk_stream(const float* __restrict__ cam) {
    __shared__ unsigned s_cnt[NH];
    __shared__ float    s_sum[NH];

    const int row  = blockIdx.x / SPLIT;
    const int part = blockIdx.x % SPLIT;
    const int t    = threadIdx.x;
    const int lane = t & 31;

    for (int i = t; i < NH; i += NT1) { s_cnt[i] = 0u; s_sum[i] = 0.f; }
    __syncthreads();

    const float4* src = (const float4*)(cam + (size_t)row * N_PER_ROW)
                        + (size_t)part * (N_PER_ROW / 4 / SPLIT);
    float* cand = g_cand + (size_t)row * CAND_CAP;

    // 16384 float4 per part; 4 independent float4 loads per thread per iter
    #pragma unroll 1
    for (int it = 0; it < 8; it++) {
        int base = it * 2048 + t;
        float4 v0 = src[base];
        float4 v1 = src[base + 512];
        float4 v2 = src[base + 1024];
        float4 v3 = src[base + 1536];
        float a[16] = {v0.x, v0.y, v0.z, v0.w, v1.x, v1.y, v1.z, v1.w,
                       v2.x, v2.y, v2.z, v2.w, v3.x, v3.y, v3.z, v3.w};
        #pragma unroll
        for (int j = 0; j < 16; j++) {
            float v = a[j];
            unsigned k = mono(__float_as_uint(v));
            bool p = (k >= KEY_175);
            unsigned m = __ballot_sync(0xffffffffu, p);
            if (p) {
                unsigned d = k - KEY_175;
                unsigned b = d >> 14; if (b > 1664u) b = 1664u;
                atomicAdd(&s_cnt[b], 1u);
                atomicAdd(&s_sum[b], v);
                int ldr = __ffs(m) - 1;
                int pos0 = 0;
                if (lane == ldr) pos0 = atomicAdd(&g_cand_cnt[row], __popc(m));
                pos0 = __shfl_sync(m, pos0, ldr);
                int pos = pos0 + __popc(m & ((1u << lane) - 1u));
                if (pos < CAND_CAP) cand[pos] = v;
            }
        }
    }
    __syncthreads();

    // flush nonzero buckets to global per-row histogram
    unsigned* hc = g_hcnt + (size_t)row * NH;
    float*    hs = g_hsum + (size_t)row * NH;
    for (int i = t; i < NH; i += NT1) {
        unsigned c = s_cnt[i];
        if (c) { atomicAdd(&hc[i], c); atomicAdd(&hs[i], s_sum[i]); }
    }
}

// ---- selection step: find bucket containing rank r (from the top) ----
// Needs NB % NT2 == 0. Returns bucket, strict-above count, strict-above sum.
template<int NB>
__device__ void sel_step(unsigned* cnt, float* sum, int r,
                         int& B, unsigned& above_out, float& sab_out,
                         unsigned* part, int* sh_selb, unsigned* sh_above, float* sh_sab) {
    const int t = threadIdx.x;
    constexpr int PB = NB / NT2;
    __syncthreads();
    if (t == 0) { *sh_selb = -1; *sh_above = 0u; *sh_sab = 0.f; }
    __syncthreads();
    unsigned p = 0;
    #pragma unroll
    for (int i = 0; i < PB; i++) p += cnt[t * PB + i];
    part[t] = p;
    __syncthreads();
    for (int d = 1; d < NT2; d <<= 1) {
        unsigned v = part[t] + ((t + d < NT2) ? part[t + d] : 0u);
        __syncthreads();
        part[t] = v;
        __syncthreads();
    }
    unsigned above = (t + 1 < NT2) ? part[t + 1] : 0u;
    unsigned ur = (unsigned)r;
    #pragma unroll
    for (int i = PB - 1; i >= 0; i--) {
        int b = t * PB + i;
        unsigned c = cnt[b];
        if (above < ur && ur <= above + c) { *sh_selb = b; *sh_above = above; }
        above += c;
    }
    __syncthreads();
    int b = *sh_selb;
    if (b >= 0) {
        float loc = 0.f;
        for (int i = t; i < NB; i += NT2)
            if (i > b) loc += sum[i];
        if (loc != 0.f) atomicAdd(sh_sab, loc);
    }
    __syncthreads();
    B = *sh_selb; above_out = *sh_above; sab_out = *sh_sab;
    __syncthreads();
}

template<int NB>
__device__ __forceinline__ void hclear(unsigned* cnt, float* sum) {
    for (int i = threadIdx.x; i < NB; i += NT2) { cnt[i] = 0u; sum[i] = 0.f; }
    __syncthreads();
}

// ---- Kernel 2: per-row final select ----
__global__ void __launch_bounds__(NT2) toptk_final(const float* __restrict__ cam,
                                                   float* __restrict__ out) {
    __shared__ unsigned s_cnt[4096];
    __shared__ float    s_sum[4096];
    __shared__ float    s_list[LCAP];
    __shared__ unsigned s_part[NT2];
    __shared__ int      s_selb;
    __shared__ unsigned s_above;
    __shared__ float    s_sab;
    __shared__ int      s_nl;

    const int row = blockIdx.x;
    const int t   = threadIdx.x;
    const int lane = t & 31;
    const int cc  = g_cand_cnt[row];

    // load per-row coarse hist (padded)
    {
        const unsigned* hc = g_hcnt + (size_t)row * NH;
        const float*    hs = g_hsum + (size_t)row * NH;
        for (int i = t; i < NHPAD; i += NT2) {
            s_cnt[i] = (i < NH) ? hc[i] : 0u;
            s_sum[i] = (i < NH) ? hs[i] : 0.f;
        }
    }
    int B; unsigned above; float sab;
    sel_step<NHPAD>(s_cnt, s_sum, K_SEL, B, above, sab, s_part, &s_selb, &s_above, &s_sab);

    bool fullrow = (B < 0) || (B == 1664) || (cc > CAND_CAP);

    if (!fullrow) {
        int r = K_SEL - (int)above;
        float S = sab;

        // gather in-bucket candidates into smem list
        if (t == 0) s_nl = 0;
        __syncthreads();
        const float* cand = g_cand + (size_t)row * CAND_CAP;
        int n_pad = (cc + 31) & ~31;
        for (int i = t; i < n_pad; i += NT2) {
            float v = (i < cc) ? cand[i] : 0.f;
            unsigned d = mono(__float_as_uint(v)) - KEY_175;
            bool p = (i < cc) && ((d >> 14) == (unsigned)B);
            unsigned m = __ballot_sync(0xffffffffu, p);
            if (p) {
                int ldr = __ffs(m) - 1;
                int pos0 = 0;
                if (lane == ldr) pos0 = atomicAdd(&s_nl, __popc(m));
                pos0 = __shfl_sync(m, pos0, ldr);
                int pos = pos0 + __popc(m & ((1u << lane) - 1u));
                if (pos < LCAP) s_list[pos] = v;
            }
        }
        __syncthreads();
        int nl = s_nl;
        const float* src; int n;
        if (nl <= LCAP) { src = s_list; n = nl; }
        else            { src = cand;   n = cc; }   // list overflow: filter full cand array

        // fine round 1: bits [7,14) of d
        hclear<256>(s_cnt, s_sum);
        for (int i = t; i < n; i += NT2) {
            float v = src[i];
            unsigned d = mono(__float_as_uint(v)) - KEY_175;
            if ((d >> 14) == (unsigned)B) {
                unsigned dig = (d >> 7) & 127u;
                atomicAdd(&s_cnt[dig], 1u);
                atomicAdd(&s_sum[dig], v);
            }
        }
        int b1; sel_step<256>(s_cnt, s_sum, r, b1, above, sab, s_part, &s_selb, &s_above, &s_sab);
        S += sab; r -= (int)above;
        unsigned pref = (((unsigned)B) << 7) | (unsigned)b1;

        // fine round 2: bits [0,7)
        hclear<256>(s_cnt, s_sum);
        for (int i = t; i < n; i += NT2) {
            float v = src[i];
            unsigned d = mono(__float_as_uint(v)) - KEY_175;
            if ((d >> 7) == pref) {
                unsigned dig = d & 127u;
                atomicAdd(&s_cnt[dig], 1u);
                atomicAdd(&s_sum[dig], v);
            }
        }
        int b0; sel_step<256>(s_cnt, s_sum, r, b0, above, sab, s_part, &s_selb, &s_above, &s_sab);
        S += sab; r -= (int)above;

        unsigned key = KEY_175 + ((pref << 7) | (unsigned)b0);
        if (t == 0) out[row] = (S + (float)r * unmono(key)) / (float)K_SEL;
    } else {
        // exact full-row radix select: 12/10/10 bits over mono keys
        const float* rowp = cam + (size_t)row * N_PER_ROW;
        int r = K_SEL; float S = 0.f;

        hclear<4096>(s_cnt, s_sum);
        for (int i = t; i < N_PER_ROW; i += NT2) {
            float v = rowp[i];
            unsigned k = mono(__float_as_uint(v));
            atomicAdd(&s_cnt[k >> 20], 1u);
            atomicAdd(&s_sum[k >> 20], v);
        }
        int B0; sel_step<4096>(s_cnt, s_sum, r, B0, above, sab, s_part, &s_selb, &s_above, &s_sab);
        S += sab; r -= (int)above;
        unsigned pref = ((unsigned)B0) << 20;

        hclear<1024>(s_cnt, s_sum);
        for (int i = t; i < N_PER_ROW; i += NT2) {
            float v = rowp[i];
            unsigned k = mono(__float_as_uint(v));
            if ((k & 0xFFF00000u) == pref) {
                unsigned dig = (k >> 10) & 1023u;
                atomicAdd(&s_cnt[dig], 1u);
                atomicAdd(&s_sum[dig], v);
            }
        }
        int d1; sel_step<1024>(s_cnt, s_sum, r, d1, above, sab, s_part, &s_selb, &s_above, &s_sab);
        S += sab; r -= (int)above;
        pref |= ((unsigned)d1) << 10;

        hclear<1024>(s_cnt, s_sum);
        for (int i = t; i < N_PER_ROW; i += NT2) {
            float v = rowp[i];
            unsigned k = mono(__float_as_uint(v));
            if ((k & 0xFFFFFC00u) == pref) {
                unsigned dig = k & 1023u;
                atomicAdd(&s_cnt[dig], 1u);
                atomicAdd(&s_sum[dig], v);
            }
        }
        int d0; sel_step<1024>(s_cnt, s_sum, r, d0, above, sab, s_part, &s_selb, &s_above, &s_sab);
        S += sab; r -= (int)above;
        pref |= (unsigned)d0;

        if (t == 0) out[row] = (S + (float)r * unmono(pref)) / (float)K_SEL;
    }
}

extern "C" void kernel_launch(void* const* d_in, const int* in_sizes, int n_in,
                              void* d_out, int out_size) {
    const float* cam = (const float*)d_in[0];
    float* out = (float*)d_out;
    toptk_zero<<<512, 512>>>();
    toptk_stream<<<ROWS * SPLIT, NT1>>>(cam);
    toptk_final<<<ROWS, NT2>>>(cam, out);
}

// round 3
// speedup vs baseline: 2.8514x; 2.8514x over previous
#include <cuda_runtime.h>
#include <cuda_bf16.h>
#include <cstdint>

// Problem: cam (32,4,512,512) f32 -> out[32,4] = mean of top 5243 per row
#define ROWS      128
#define N_PER_ROW (512*512)     // 262144
#define K_SEL     5243
#define SPLIT     8             // CTAs per row in streaming kernel
#define NT1       256
#define NT2       256
#define PCAP      3072          // per-part candidate cap (expect ~1314, sd 35)
#define NH        1665          // fine buckets + overflow
#define NHPAD     1792
#define BITS_175  0x3FE00000u   // raw bits of 1.75f

// ---- static device scratch (fully rewritten every run; no zeroing needed) ----
__device__ float g_cand[(size_t)ROWS * SPLIT * PCAP];
__device__ int   g_pcnt[ROWS * SPLIT];

__device__ __forceinline__ unsigned mono(unsigned x) {
    return (x & 0x80000000u) ? ~x : (x | 0x80000000u);
}
__device__ __forceinline__ float unmono(unsigned k) {
    unsigned b = (k & 0x80000000u) ? (k ^ 0x80000000u) : ~k;
    return __uint_as_float(b);
}

// ---- Kernel 1: stream 128MB once; compact values >= 1.75 into per-CTA segment ----
__global__ void __launch_bounds__(NT1) toptk_stream(const float* __restrict__ cam) {
    __shared__ float s_stage[PCAP];
    __shared__ int   s_cc;

    const int bid  = blockIdx.x;
    const int row  = bid / SPLIT;
    const int part = bid % SPLIT;
    const int t    = threadIdx.x;
    const int lane = t & 31;
    const unsigned lmask_lt = (1u << lane) - 1u;

    if (t == 0) s_cc = 0;
    __syncthreads();

    const float4* src = (const float4*)(cam + (size_t)row * N_PER_ROW)
                        + (size_t)part * (N_PER_ROW / 4 / SPLIT);

    #pragma unroll 1
    for (int it = 0; it < 8; it++) {
        int base = it * 1024 + t;
        float4 v0 = src[base];
        float4 v1 = src[base + 256];
        float4 v2 = src[base + 512];
        float4 v3 = src[base + 768];
        float a[16] = {v0.x, v0.y, v0.z, v0.w, v1.x, v1.y, v1.z, v1.w,
                       v2.x, v2.y, v2.z, v2.w, v3.x, v3.y, v3.z, v3.w};
        #pragma unroll
        for (int j = 0; j < 16; j++) {
            float v = a[j];
            // positive v >= 1.75  <=>  signed int bits >= 0x3FE00000
            bool p = ((int)__float_as_uint(v) >= (int)BITS_175);
            unsigned m = __ballot_sync(0xffffffffu, p);
            if (p) {
                int ldr = __ffs(m) - 1;
                int pos0 = 0;
                if (lane == ldr) pos0 = atomicAdd(&s_cc, __popc(m));
                pos0 = __shfl_sync(m, pos0, ldr);
                int pos = pos0 + __popc(m & lmask_lt);
                if (pos < PCAP) s_stage[pos] = v;
            }
        }
    }
    __syncthreads();

    int cc = s_cc;
    if (t == 0) g_pcnt[bid] = cc;       // raw count (may exceed PCAP -> flag)
    int w = cc < PCAP ? cc : PCAP;
    float* dst = g_cand + (size_t)bid * PCAP;
    for (int i = t; i < w; i += NT1) dst[i] = s_stage[i];
}

// ---- selection helper: bucket containing rank r from the top ----
template<int NB>
__device__ void sel_step(unsigned* cnt, float* sum, int r,
                         int& B, unsigned& above_out, float& sab_out,
                         unsigned* part, int* sh_selb, unsigned* sh_above, float* sh_sab) {
    const int t = threadIdx.x;
    constexpr int PB = NB / NT2;
    __syncthreads();
    if (t == 0) { *sh_selb = -1; *sh_above = 0u; *sh_sab = 0.f; }
    __syncthreads();
    unsigned p = 0;
    #pragma unroll
    for (int i = 0; i < PB; i++) p += cnt[t * PB + i];
    part[t] = p;
    __syncthreads();
    for (int d = 1; d < NT2; d <<= 1) {
        unsigned v = part[t] + ((t + d < NT2) ? part[t + d] : 0u);
        __syncthreads();
        part[t] = v;
        __syncthreads();
    }
    unsigned above = (t + 1 < NT2) ? part[t + 1] : 0u;
    unsigned ur = (unsigned)r;
    #pragma unroll
    for (int i = PB - 1; i >= 0; i--) {
        int b = t * PB + i;
        unsigned c = cnt[b];
        if (above < ur && ur <= above + c) { *sh_selb = b; *sh_above = above; }
        above += c;
    }
    __syncthreads();
    int b = *sh_selb;
    if (b >= 0) {
        float loc = 0.f;
        for (int i = t; i < NB; i += NT2)
            if (i > b) loc += sum[i];
        if (loc != 0.f) atomicAdd(sh_sab, loc);
    }
    __syncthreads();
    B = *sh_selb; above_out = *sh_above; sab_out = *sh_sab;
    __syncthreads();
}

template<int NB>
__device__ __forceinline__ void hclear(unsigned* cnt, float* sum) {
    for (int i = threadIdx.x; i < NB; i += NT2) { cnt[i] = 0u; sum[i] = 0.f; }
    __syncthreads();
}

// ---- Kernel 2: per-row exact select over candidates (or full-row fallback) ----
__global__ void __launch_bounds__(NT2) toptk_final(const float* __restrict__ cam,
                                                   float* __restrict__ out) {
    __shared__ unsigned s_cnt[4096];
    __shared__ float    s_sum[4096];
    __shared__ unsigned s_part[NT2];
    __shared__ int      s_selb;
    __shared__ unsigned s_above;
    __shared__ float    s_sab;

    const int row = blockIdx.x;
    const int t   = threadIdx.x;

    int pcnt[SPLIT];
    int cc = 0; bool bad = false;
    #pragma unroll
    for (int p = 0; p < SPLIT; p++) {
        int c = g_pcnt[row * SPLIT + p];
        if (c > PCAP) bad = true;
        pcnt[p] = c > PCAP ? PCAP : c;
        cc += pcnt[p];
    }
    int B; unsigned above; float sab;

    if (!bad && cc >= K_SEL) {
        // ---- fast path: 3-round radix over ~10.5K L2-resident candidates ----
        // round 1: 1664 fine buckets on (bits - 0x3FE00000) >> 14 (values all positive)
        hclear<NHPAD>(s_cnt, s_sum);
        #pragma unroll
        for (int p = 0; p < SPLIT; p++) {
            const float* seg = g_cand + (size_t)(row * SPLIT + p) * PCAP;
            for (int i = t; i < pcnt[p]; i += NT2) {
                float v = seg[i];
                unsigned d = __float_as_uint(v) - BITS_175;
                unsigned b = d >> 14; if (b > 1664u) b = 1664u;
                atomicAdd(&s_cnt[b], 1u);
                atomicAdd(&s_sum[b], v);
            }
        }
        sel_step<NHPAD>(s_cnt, s_sum, K_SEL, B, above, sab, s_part, &s_selb, &s_above, &s_sab);

        if (B >= 0 && B != 1664) {
            int r = K_SEL - (int)above;
            float S = sab;

            // round 2: bits [7,14)
            hclear<256>(s_cnt, s_sum);
            #pragma unroll
            for (int p = 0; p < SPLIT; p++) {
                const float* seg = g_cand + (size_t)(row * SPLIT + p) * PCAP;
                for (int i = t; i < pcnt[p]; i += NT2) {
                    float v = seg[i];
                    unsigned d = __float_as_uint(v) - BITS_175;
                    if ((d >> 14) == (unsigned)B) {
                        atomicAdd(&s_cnt[(d >> 7) & 127u], 1u);
                        atomicAdd(&s_sum[(d >> 7) & 127u], v);
                    }
                }
            }
            int b1; sel_step<256>(s_cnt, s_sum, r, b1, above, sab, s_part, &s_selb, &s_above, &s_sab);
            S += sab; r -= (int)above;
            unsigned pref = (((unsigned)B) << 7) | (unsigned)b1;

            // round 3: bits [0,7)
            hclear<256>(s_cnt, s_sum);
            #pragma unroll
            for (int p = 0; p < SPLIT; p++) {
                const float* seg = g_cand + (size_t)(row * SPLIT + p) * PCAP;
                for (int i = t; i < pcnt[p]; i += NT2) {
                    float v = seg[i];
                    unsigned d = __float_as_uint(v) - BITS_175;
                    if ((d >> 7) == pref) {
                        atomicAdd(&s_cnt[d & 127u], 1u);
                        atomicAdd(&s_sum[d & 127u], v);
                    }
                }
            }
            int b0; sel_step<256>(s_cnt, s_sum, r, b0, above, sab, s_part, &s_selb, &s_above, &s_sab);
            S += sab; r -= (int)above;

            float vt = __uint_as_float(BITS_175 + ((pref << 7) | (unsigned)b0));
            if (t == 0) out[row] = (S + (float)r * vt) / (float)K_SEL;
            return;
        }
        // selected overflow bucket (v >= 16): fall through to exact full-row
    }

    // ---- exact full-row fallback: 12/10/10-bit radix over mono keys ----
    {
        const float* rowp = cam + (size_t)row * N_PER_ROW;
        int r = K_SEL; float S = 0.f;

        hclear<4096>(s_cnt, s_sum);
        for (int i = t; i < N_PER_ROW; i += NT2) {
            float v = rowp[i];
            unsigned k = mono(__float_as_uint(v));
            atomicAdd(&s_cnt[k >> 20], 1u);
            atomicAdd(&s_sum[k >> 20], v);
        }
        int B0; sel_step<4096>(s_cnt, s_sum, r, B0, above, sab, s_part, &s_selb, &s_above, &s_sab);
        S += sab; r -= (int)above;
        unsigned pref = ((unsigned)B0) << 20;

        hclear<1024>(s_cnt, s_sum);
        for (int i = t; i < N_PER_ROW; i += NT2) {
            float v = rowp[i];
            unsigned k = mono(__float_as_uint(v));
            if ((k & 0xFFF00000u) == pref) {
                atomicAdd(&s_cnt[(k >> 10) & 1023u], 1u);
                atomicAdd(&s_sum[(k >> 10) & 1023u], v);
            }
        }
        int d1; sel_step<1024>(s_cnt, s_sum, r, d1, above, sab, s_part, &s_selb, &s_above, &s_sab);
        S += sab; r -= (int)above;
        pref |= ((unsigned)d1) << 10;

        hclear<1024>(s_cnt, s_sum);
        for (int i = t; i < N_PER_ROW; i += NT2) {
            float v = rowp[i];
            unsigned k = mono(__float_as_uint(v));
            if ((k & 0xFFFFFC00u) == pref) {
                atomicAdd(&s_cnt[k & 1023u], 1u);
                atomicAdd(&s_sum[k & 1023u], v);
            }
        }
        int d0; sel_step<1024>(s_cnt, s_sum, r, d0, above, sab, s_part, &s_selb, &s_above, &s_sab);
        S += sab; r -= (int)above;
        pref |= (unsigned)d0;

        if (t == 0) out[row] = (S + (float)r * unmono(pref)) / (float)K_SEL;
    }
}

extern "C" void kernel_launch(void* const* d_in, const int* in_sizes, int n_in,
                              void* d_out, int out_size) {
    const float* cam = (const float*)d_in[0];
    float* out = (float*)d_out;
    toptk_stream<<<ROWS * SPLIT, NT1>>>(cam);
    toptk_final<<<ROWS, NT2>>>(cam, out);
}

// round 5
// speedup vs baseline: 6.8186x; 2.3913x over previous
#include <cuda_runtime.h>
#include <cuda_bf16.h>
#include <cstdint>

// Problem: cam (32,4,512,512) f32 -> out[32,4] = mean of top 5243 per row
#define ROWS      128
#define N_PER_ROW (512*512)     // 262144
#define K_SEL     5243
#define SPLIT     8             // stream CTAs per row
#define NT1       256
#define NWARP1    (NT1/32)      // 8
#define WCAP      320           // per-warp stage cap (mean 164, sd ~13 -> +12 sigma)
#define PCAP      (NWARP1*WCAP) // 2560 per-part cap
#define NT2       512
#define CCAP      12288         // smem candidate cap (cc mean ~10511, sd ~100)
#define NHPAD     2048          // 1664 fine buckets + overflow, padded
#define BITS_175  0x3FE00000u   // raw bits of 1.75f

// ---- static device scratch (fully rewritten each run; no zeroing kernel) ----
__device__ float g_cand[(size_t)ROWS * SPLIT * PCAP];
__device__ int   g_pcnt[ROWS * SPLIT];

__device__ __forceinline__ unsigned mono(unsigned x) {
    return (x & 0x80000000u) ? ~x : (x | 0x80000000u);
}
__device__ __forceinline__ float unmono(unsigned k) {
    unsigned b = (k & 0x80000000u) ? (k ^ 0x80000000u) : ~k;
    return __uint_as_float(b);
}

// ---- Kernel 1: stream 128MB; compact v>=1.75 via per-warp stage (NO atomics) ----
__global__ void __launch_bounds__(NT1) toptk_stream(const float* __restrict__ cam) {
    __shared__ float s_stage[NWARP1 * WCAP];
    __shared__ int   s_wcnt[NWARP1];

    const int bid  = blockIdx.x;
    const int row  = bid / SPLIT;
    const int part = bid % SPLIT;
    const int t    = threadIdx.x;
    const int wid  = t >> 5;
    const int lane = t & 31;
    const unsigned lmask_lt = (1u << lane) - 1u;

    const float4* src = (const float4*)(cam + (size_t)row * N_PER_ROW)
                        + (size_t)part * (N_PER_ROW / 4 / SPLIT);   // 8192 float4

    int wcnt = 0;  // identical in every lane of the warp
    float4 c0 = src[t], c1 = src[t + 256], c2 = src[t + 512], c3 = src[t + 768];

    #pragma unroll 1
    for (int it = 0; it < 8; it++) {
        float4 n0 = c0, n1 = c1, n2 = c2, n3 = c3;
        if (it < 7) {
            int b = (it + 1) * 1024 + t;
            n0 = src[b]; n1 = src[b + 256]; n2 = src[b + 512]; n3 = src[b + 768];
        }
        float a[16] = {c0.x, c0.y, c0.z, c0.w, c1.x, c1.y, c1.z, c1.w,
                       c2.x, c2.y, c2.z, c2.w, c3.x, c3.y, c3.z, c3.w};
        #pragma unroll
        for (int j = 0; j < 16; j++) {
            float v = a[j];
            bool p = ((int)__float_as_uint(v) >= (int)BITS_175);  // positive v >= 1.75
            unsigned m = __ballot_sync(0xffffffffu, p);
            if (p) {
                int pos = wcnt + __popc(m & lmask_lt);
                if (pos < WCAP) s_stage[wid * WCAP + pos] = v;
            }
            wcnt += __popc(m);
        }
        c0 = n0; c1 = n1; c2 = n2; c3 = n3;
    }

    if (lane == 0) s_wcnt[wid] = wcnt;
    __syncthreads();

    int tot = 0, off = 0; bool bad = false;
    #pragma unroll
    for (int w = 0; w < NWARP1; w++) {
        int c = s_wcnt[w];
        if (c > WCAP) bad = true;
        int cl = c < WCAP ? c : WCAP;
        if (w < wid) off += cl;
        tot += cl;
    }
    int mycnt = s_wcnt[wid]; if (mycnt > WCAP) mycnt = WCAP;
    float* dst = g_cand + (size_t)bid * PCAP + off;
    for (int i = lane; i < mycnt; i += 32) dst[i] = s_stage[wid * WCAP + i];
    if (t == 0) g_pcnt[bid] = bad ? -1 : tot;
}

// ---- count-only rank-select: bucket containing rank r from the top ----
template<int NB>
__device__ void sel_step(const unsigned* cnt, int r, int& B, unsigned& above_out,
                         unsigned* part, int* sh_selb, unsigned* sh_above) {
    const int t = threadIdx.x;
    constexpr int PB = NB / NT2;
    __syncthreads();
    if (t == 0) { *sh_selb = -1; *sh_above = 0u; }
    __syncthreads();
    unsigned p = 0;
    #pragma unroll
    for (int i = 0; i < PB; i++) p += cnt[t * PB + i];
    part[t] = p;
    __syncthreads();
    for (int d = 1; d < NT2; d <<= 1) {
        unsigned v = part[t] + ((t + d < NT2) ? part[t + d] : 0u);
        __syncthreads();
        part[t] = v;
        __syncthreads();
    }
    unsigned above = (t + 1 < NT2) ? part[t + 1] : 0u;
    unsigned ur = (unsigned)r;
    #pragma unroll
    for (int i = PB - 1; i >= 0; i--) {
        int b = t * PB + i;
        unsigned c = cnt[b];
        if (above < ur && ur <= above + c) { *sh_selb = b; *sh_above = above; }
        above += c;
    }
    __syncthreads();
    B = *sh_selb; above_out = *sh_above;
    __syncthreads();
}

template<int NB>
__device__ __forceinline__ void hclear(unsigned* cnt) {
    for (int i = threadIdx.x; i < NB; i += NT2) cnt[i] = 0u;
    __syncthreads();
}

// block reduce (sum, count); result valid on thread 0
__device__ void block_reduce(float ls, unsigned lc, float* s_rs, unsigned* s_rc,
                             float& S, unsigned& C) {
    const int t = threadIdx.x, lane = t & 31, wid = t >> 5;
    #pragma unroll
    for (int d = 16; d > 0; d >>= 1) {
        ls += __shfl_down_sync(0xffffffffu, ls, d);
        lc += __shfl_down_sync(0xffffffffu, lc, d);
    }
    if (lane == 0) { s_rs[wid] = ls; s_rc[wid] = lc; }
    __syncthreads();
    if (wid == 0) {
        ls = (lane < NT2 / 32) ? s_rs[lane] : 0.f;
        lc = (lane < NT2 / 32) ? s_rc[lane] : 0u;
        #pragma unroll
        for (int d = 16; d > 0; d >>= 1) {
            ls += __shfl_down_sync(0xffffffffu, ls, d);
            lc += __shfl_down_sync(0xffffffffu, lc, d);
        }
    }
    S = ls; C = lc;   // valid on thread 0 only
}

// ---- Kernel 2: per-row exact select; candidates cached in smem ----
__global__ void __launch_bounds__(NT2) toptk_final(const float* __restrict__ cam,
                                                   float* __restrict__ out) {
    extern __shared__ float s_cand[];     // CCAP floats (48KB dynamic, opt-in)
    __shared__ unsigned s_cnt[4096];
    __shared__ unsigned s_part[NT2];
    __shared__ int      s_selb;
    __shared__ unsigned s_above;
    __shared__ float    s_rs[NT2 / 32];
    __shared__ unsigned s_rc[NT2 / 32];

    const int row = blockIdx.x;
    const int t   = threadIdx.x;

    int pcnt[SPLIT]; int cc = 0; bool bad = false;
    #pragma unroll
    for (int p = 0; p < SPLIT; p++) {
        int c = g_pcnt[row * SPLIT + p];
        if (c < 0 || c > PCAP) { bad = true; c = 0; }
        pcnt[p] = c; cc += c;
    }

    if (!bad && cc >= K_SEL && cc <= CCAP) {
        // gather all candidates into smem (single latency-burst read)
        int off = 0;
        #pragma unroll
        for (int p = 0; p < SPLIT; p++) {
            const float* seg = g_cand + (size_t)(row * SPLIT + p) * PCAP;
            for (int i = t; i < pcnt[p]; i += NT2) s_cand[off + i] = seg[i];
            off += pcnt[p];
        }
        __syncthreads();

        // round 1: 1664 fine buckets (bits-1.75f) >> 14, count only
        hclear<NHPAD>(s_cnt);
        for (int i = t; i < cc; i += NT2) {
            unsigned d = __float_as_uint(s_cand[i]) - BITS_175;
            unsigned b = d >> 14; if (b > 1664u) b = 1664u;
            atomicAdd(&s_cnt[b], 1u);
        }
        int B; unsigned above;
        sel_step<NHPAD>(s_cnt, K_SEL, B, above, s_part, &s_selb, &s_above);

        if (B >= 0 && B != 1664) {
            int r1 = K_SEL - (int)above;

            // round 2: bits [7,14)
            hclear<512>(s_cnt);
            for (int i = t; i < cc; i += NT2) {
                unsigned d = __float_as_uint(s_cand[i]) - BITS_175;
                if ((d >> 14) == (unsigned)B) atomicAdd(&s_cnt[(d >> 7) & 127u], 1u);
            }
            int b1; sel_step<512>(s_cnt, r1, b1, above, s_part, &s_selb, &s_above);
            int r2 = r1 - (int)above;
            unsigned pref = (((unsigned)B) << 7) | (unsigned)b1;

            // round 3: bits [0,7)
            hclear<512>(s_cnt);
            for (int i = t; i < cc; i += NT2) {
                unsigned d = __float_as_uint(s_cand[i]) - BITS_175;
                if ((d >> 7) == pref) atomicAdd(&s_cnt[d & 127u], 1u);
            }
            int b0; sel_step<512>(s_cnt, r2, b0, above, s_part, &s_selb, &s_above);

            float vt = __uint_as_float(BITS_175 + ((pref << 7) | (unsigned)b0));

            // atomic-free sum pass over smem candidates
            float ls = 0.f; unsigned lc = 0u;
            for (int i = t; i < cc; i += NT2) {
                float v = s_cand[i];
                if (v > vt) { ls += v; lc++; }
            }
            float S; unsigned C;
            block_reduce(ls, lc, s_rs, s_rc, S, C);
            if (t == 0) out[row] = (S + (float)(K_SEL - (int)C) * vt) / (float)K_SEL;
            return;
        }
        // degenerate bucket -> fall through to exact full-row
        __syncthreads();
    }

    // ---- exact full-row fallback: 12/10/10-bit count radix over mono keys ----
    {
        const float* rowp = cam + (size_t)row * N_PER_ROW;
        int r = K_SEL; unsigned above;

        hclear<4096>(s_cnt);
        for (int i = t; i < N_PER_ROW; i += NT2)
            atomicAdd(&s_cnt[mono(__float_as_uint(rowp[i])) >> 20], 1u);
        int B0; sel_step<4096>(s_cnt, r, B0, above, s_part, &s_selb, &s_above);
        r -= (int)above;
        unsigned pref = ((unsigned)B0) << 20;

        hclear<1024>(s_cnt);
        for (int i = t; i < N_PER_ROW; i += NT2) {
            unsigned k = mono(__float_as_uint(rowp[i]));
            if ((k & 0xFFF00000u) == pref) atomicAdd(&s_cnt[(k >> 10) & 1023u], 1u);
        }
        int d1; sel_step<1024>(s_cnt, r, d1, above, s_part, &s_selb, &s_above);
        r -= (int)above;
        pref |= ((unsigned)d1) << 10;

        hclear<1024>(s_cnt);
        for (int i = t; i < N_PER_ROW; i += NT2) {
            unsigned k = mono(__float_as_uint(rowp[i]));
            if ((k & 0xFFFFFC00u) == pref) atomicAdd(&s_cnt[k & 1023u], 1u);
        }
        int d0; sel_step<1024>(s_cnt, r, d0, above, s_part, &s_selb, &s_above);
        unsigned kt = pref | (unsigned)d0;

        float ls = 0.f; unsigned lc = 0u;
        for (int i = t; i < N_PER_ROW; i += NT2) {
            float v = rowp[i];
            if (mono(__float_as_uint(v)) > kt) { ls += v; lc++; }
        }
        float S; unsigned C;
        block_reduce(ls, lc, s_rs, s_rc, S, C);
        if (t == 0) out[row] = (S + (float)(K_SEL - (int)C) * unmono(kt)) / (float)K_SEL;
    }
}

extern "C" void kernel_launch(void* const* d_in, const int* in_sizes, int n_in,
                              void* d_out, int out_size) {
    const float* cam = (const float*)d_in[0];
    float* out = (float*)d_out;
    // Opt-in for 48KB dynamic smem on top of ~18.6KB static (attribute set is
    // not a stream op / allocation; safe under graph capture, idempotent).
    cudaFuncSetAttribute(toptk_final, cudaFuncAttributeMaxDynamicSharedMemorySize,
                         CCAP * sizeof(float));
    toptk_stream<<<ROWS * SPLIT, NT1>>>(cam);
    toptk_final<<<ROWS, NT2, CCAP * sizeof(float)>>>(cam, out);
}

// round 6
// speedup vs baseline: 7.1286x; 1.0455x over previous
#include <cuda_runtime.h>
#include <cuda_bf16.h>
#include <cstdint>

// Problem: cam (32,4,512,512) f32 -> out[32,4] = mean of top 5243 per row
#define ROWS      128
#define N_PER_ROW (512*512)     // 262144
#define K_SEL     5243
#define SPLIT     16            // stream CTAs per row (finer grain for balance)
#define NT1       256
#define NWARP1    (NT1/32)      // 8
#define WCAP      192           // per-warp stage cap (mean 82, sd ~9 -> +12 sigma)
#define PCAP      (NWARP1*WCAP) // 1536 per-part cap
#define NT2       512
#define NW2       (NT2/32)      // 16
#define CCAP      12288         // smem candidate cap (cc mean ~10511, sd ~100)
#define NHPAD     2048          // 1664 fine buckets + overflow, padded
#define BITS_175  0x3FE00000u   // raw bits of 1.75f

// ---- static device scratch (fully rewritten each run; no zeroing kernel) ----
__device__ float g_cand[(size_t)ROWS * SPLIT * PCAP];
__device__ int   g_pcnt[ROWS * SPLIT];

__device__ __forceinline__ unsigned mono(unsigned x) {
    return (x & 0x80000000u) ? ~x : (x | 0x80000000u);
}
__device__ __forceinline__ float unmono(unsigned k) {
    unsigned b = (k & 0x80000000u) ? (k ^ 0x80000000u) : ~k;
    return __uint_as_float(b);
}

// ---- Kernel 1: stream 128MB; compact v>=1.75 via per-warp stage (NO atomics) ----
__global__ void __launch_bounds__(NT1) toptk_stream(const float* __restrict__ cam) {
    __shared__ float s_stage[NWARP1 * WCAP];
    __shared__ int   s_wcnt[NWARP1];

    const int bid  = blockIdx.x;
    const int row  = bid / SPLIT;
    const int part = bid % SPLIT;
    const int t    = threadIdx.x;
    const int wid  = t >> 5;
    const int lane = t & 31;
    const unsigned lmask_lt = (1u << lane) - 1u;

    const float4* src = (const float4*)(cam + (size_t)row * N_PER_ROW)
                        + (size_t)part * (N_PER_ROW / 4 / SPLIT);   // 4096 float4

    int wcnt = 0;  // identical in every lane of the warp
    float4 c0 = __ldcs(&src[t]),       c1 = __ldcs(&src[t + 256]),
           c2 = __ldcs(&src[t + 512]), c3 = __ldcs(&src[t + 768]);

    #pragma unroll 1
    for (int it = 0; it < 4; it++) {
        float4 n0 = c0, n1 = c1, n2 = c2, n3 = c3;
        if (it < 3) {
            int b = (it + 1) * 1024 + t;
            n0 = __ldcs(&src[b]);       n1 = __ldcs(&src[b + 256]);
            n2 = __ldcs(&src[b + 512]); n3 = __ldcs(&src[b + 768]);
        }
        float a[16] = {c0.x, c0.y, c0.z, c0.w, c1.x, c1.y, c1.z, c1.w,
                       c2.x, c2.y, c2.z, c2.w, c3.x, c3.y, c3.z, c3.w};
        #pragma unroll
        for (int j = 0; j < 16; j++) {
            float v = a[j];
            bool p = ((int)__float_as_uint(v) >= (int)BITS_175);  // positive v >= 1.75
            unsigned m = __ballot_sync(0xffffffffu, p);
            if (p) {
                int pos = wcnt + __popc(m & lmask_lt);
                if (pos < WCAP) s_stage[wid * WCAP + pos] = v;
            }
            wcnt += __popc(m);
        }
        c0 = n0; c1 = n1; c2 = n2; c3 = n3;
    }

    if (lane == 0) s_wcnt[wid] = wcnt;
    __syncthreads();

    int tot = 0, off = 0; bool bad = false;
    #pragma unroll
    for (int w = 0; w < NWARP1; w++) {
        int c = s_wcnt[w];
        if (c > WCAP) bad = true;
        int cl = c < WCAP ? c : WCAP;
        if (w < wid) off += cl;
        tot += cl;
    }
    int mycnt = s_wcnt[wid]; if (mycnt > WCAP) mycnt = WCAP;
    float* dst = g_cand + (size_t)bid * PCAP + off;
    for (int i = lane; i < mycnt; i += 32) dst[i] = s_stage[wid * WCAP + i];
    if (t == 0) g_pcnt[bid] = bad ? -1 : tot;
}

// ---- hclear: zero histogram, reset select slot; ends with barrier ----
template<int NB>
__device__ __forceinline__ void hclear(unsigned* cnt, int* sh_selb) {
    for (int i = threadIdx.x; i < NB; i += NT2) cnt[i] = 0u;
    if (threadIdx.x == 0) *sh_selb = -1;
    __syncthreads();
}

// ---- count-only rank-select, two-level shfl suffix scan (4 barriers) ----
// Requires sh_selb pre-set to -1 (done by hclear). Finds bucket with
// countAbove(b) < r <= countAbove(b)+cnt[b]; buckets ascending in value.
template<int NB>
__device__ void sel_step(const unsigned* cnt, int r, int& B, unsigned& above_out,
                         unsigned* s_wtot, unsigned* s_wsuf,
                         int* sh_selb, unsigned* sh_above) {
    const int t = threadIdx.x, lane = t & 31, wid = t >> 5;
    constexpr int PB = (NB + NT2 - 1) / NT2;
    __syncthreads();   // histogram pass complete

    unsigned p = 0;
    #pragma unroll
    for (int i = 0; i < PB; i++) {
        int b = t * PB + i;
        if (b < NB) p += cnt[b];
    }
    // warp inclusive suffix scan
    unsigned incl = p;
    #pragma unroll
    for (int d = 1; d < 32; d <<= 1) {
        unsigned o = __shfl_down_sync(0xffffffffu, incl, d);
        if (lane + d < 32) incl += o;
    }
    if (lane == 0) s_wtot[wid] = incl;
    __syncthreads();
    if (wid == 0) {
        unsigned v = (lane < NW2) ? s_wtot[lane] : 0u;
        unsigned wincl = v;
        #pragma unroll
        for (int d = 1; d < NW2; d <<= 1) {
            unsigned o = __shfl_down_sync(0xffffffffu, wincl, d);
            if (lane + d < 32) wincl += o;
        }
        if (lane < NW2) s_wsuf[lane] = wincl - v;   // exclusive suffix over warps
    }
    __syncthreads();

    unsigned above = s_wsuf[wid] + (incl - p);   // count strictly above my chunk
    unsigned ur = (unsigned)r;
    #pragma unroll
    for (int i = PB - 1; i >= 0; i--) {
        int b = t * PB + i;
        unsigned c = (b < NB) ? cnt[b] : 0u;
        if (above < ur && ur <= above + c) { *sh_selb = b; *sh_above = above; }
        above += c;
    }
    __syncthreads();
    B = *sh_selb; above_out = *sh_above;
}

// block reduce (sum, count); result valid on thread 0
__device__ void block_reduce(float ls, unsigned lc, float* s_rs, unsigned* s_rc,
                             float& S, unsigned& C) {
    const int t = threadIdx.x, lane = t & 31, wid = t >> 5;
    #pragma unroll
    for (int d = 16; d > 0; d >>= 1) {
        ls += __shfl_down_sync(0xffffffffu, ls, d);
        lc += __shfl_down_sync(0xffffffffu, lc, d);
    }
    if (lane == 0) { s_rs[wid] = ls; s_rc[wid] = lc; }
    __syncthreads();
    if (wid == 0) {
        ls = (lane < NW2) ? s_rs[lane] : 0.f;
        lc = (lane < NW2) ? s_rc[lane] : 0u;
        #pragma unroll
        for (int d = 16; d > 0; d >>= 1) {
            ls += __shfl_down_sync(0xffffffffu, ls, d);
            lc += __shfl_down_sync(0xffffffffu, lc, d);
        }
    }
    S = ls; C = lc;   // valid on thread 0 only
}

// ---- Kernel 2: per-row exact select; candidates cached in smem ----
__global__ void __launch_bounds__(NT2) toptk_final(const float* __restrict__ cam,
                                                   float* __restrict__ out) {
    extern __shared__ float s_cand[];     // CCAP floats (48KB dynamic, opt-in)
    __shared__ unsigned s_cnt[4096];
    __shared__ unsigned s_wtot[NW2];
    __shared__ unsigned s_wsuf[NW2];
    __shared__ int      s_selb;
    __shared__ unsigned s_above;
    __shared__ float    s_rs[NW2];
    __shared__ unsigned s_rc[NW2];

    const int row = blockIdx.x;
    const int t   = threadIdx.x;

    int pcnt[SPLIT]; int cc = 0; bool bad = false;
    #pragma unroll
    for (int p = 0; p < SPLIT; p++) {
        int c = g_pcnt[row * SPLIT + p];
        if (c < 0 || c > PCAP) { bad = true; c = 0; }
        pcnt[p] = c; cc += c;
    }

    if (!bad && cc >= K_SEL && cc <= CCAP) {
        // gather all candidates into smem (single latency-burst read)
        int off = 0;
        #pragma unroll
        for (int p = 0; p < SPLIT; p++) {
            const float* seg = g_cand + (size_t)(row * SPLIT + p) * PCAP;
            for (int i = t; i < pcnt[p]; i += NT2) s_cand[off + i] = seg[i];
            off += pcnt[p];
        }

        // round 1: 1664 fine buckets (bits-1.75f) >> 14, count only
        hclear<NHPAD>(s_cnt, &s_selb);     // barrier orders gather too
        for (int i = t; i < cc; i += NT2) {
            unsigned d = __float_as_uint(s_cand[i]) - BITS_175;
            unsigned b = d >> 14; if (b > 1664u) b = 1664u;
            atomicAdd(&s_cnt[b], 1u);
        }
        int B; unsigned above;
        sel_step<NHPAD>(s_cnt, K_SEL, B, above, s_wtot, s_wsuf, &s_selb, &s_above);

        if (B >= 0 && B != 1664) {
            int r1 = K_SEL - (int)above;

            // round 2: bits [7,14)
            hclear<128>(s_cnt, &s_selb);
            for (int i = t; i < cc; i += NT2) {
                unsigned d = __float_as_uint(s_cand[i]) - BITS_175;
                if ((d >> 14) == (unsigned)B) atomicAdd(&s_cnt[(d >> 7) & 127u], 1u);
            }
            int b1; sel_step<128>(s_cnt, r1, b1, above, s_wtot, s_wsuf, &s_selb, &s_above);
            int r2 = r1 - (int)above;
            unsigned pref = (((unsigned)B) << 7) | (unsigned)b1;

            // round 3: bits [0,7)
            hclear<128>(s_cnt, &s_selb);
            for (int i = t; i < cc; i += NT2) {
                unsigned d = __float_as_uint(s_cand[i]) - BITS_175;
                if ((d >> 7) == pref) atomicAdd(&s_cnt[d & 127u], 1u);
            }
            int b0; sel_step<128>(s_cnt, r2, b0, above, s_wtot, s_wsuf, &s_selb, &s_above);

            float vt = __uint_as_float(BITS_175 + ((pref << 7) | (unsigned)b0));

            // atomic-free sum pass over smem candidates
            float ls = 0.f; unsigned lc = 0u;
            for (int i = t; i < cc; i += NT2) {
                float v = s_cand[i];
                if (v > vt) { ls += v; lc++; }
            }
            float S; unsigned C;
            block_reduce(ls, lc, s_rs, s_rc, S, C);
            if (t == 0) out[row] = (S + (float)(K_SEL - (int)C) * vt) / (float)K_SEL;
            return;
        }
        // degenerate bucket -> fall through to exact full-row
        __syncthreads();
    }

    // ---- exact full-row fallback: 12/10/10-bit count radix over mono keys ----
    {
        const float* rowp = cam + (size_t)row * N_PER_ROW;
        int r = K_SEL; unsigned above;

        hclear<4096>(s_cnt, &s_selb);
        for (int i = t; i < N_PER_ROW; i += NT2)
            atomicAdd(&s_cnt[mono(__float_as_uint(rowp[i])) >> 20], 1u);
        int B0; sel_step<4096>(s_cnt, r, B0, above, s_wtot, s_wsuf, &s_selb, &s_above);
        r -= (int)above;
        unsigned pref = ((unsigned)B0) << 20;

        hclear<1024>(s_cnt, &s_selb);
        for (int i = t; i < N_PER_ROW; i += NT2) {
            unsigned k = mono(__float_as_uint(rowp[i]));
            if ((k & 0xFFF00000u) == pref) atomicAdd(&s_cnt[(k >> 10) & 1023u], 1u);
        }
        int d1; sel_step<1024>(s_cnt, r, d1, above, s_wtot, s_wsuf, &s_selb, &s_above);
        r -= (int)above;
        pref |= ((unsigned)d1) << 10;

        hclear<1024>(s_cnt, &s_selb);
        for (int i = t; i < N_PER_ROW; i += NT2) {
            unsigned k = mono(__float_as_uint(rowp[i]));
            if ((k & 0xFFFFFC00u) == pref) atomicAdd(&s_cnt[k & 1023u], 1u);
        }
        int d0; sel_step<1024>(s_cnt, r, d0, above, s_wtot, s_wsuf, &s_selb, &s_above);
        unsigned kt = pref | (unsigned)d0;

        float ls = 0.f; unsigned lc = 0u;
        for (int i = t; i < N_PER_ROW; i += NT2) {
            float v = rowp[i];
            if (mono(__float_as_uint(v)) > kt) { ls += v; lc++; }
        }
        float S; unsigned C;
        block_reduce(ls, lc, s_rs, s_rc, S, C);
        if (t == 0) out[row] = (S + (float)(K_SEL - (int)C) * unmono(kt)) / (float)K_SEL;
    }
}

extern "C" void kernel_launch(void* const* d_in, const int* in_sizes, int n_in,
                              void* d_out, int out_size) {
    const float* cam = (const float*)d_in[0];
    float* out = (float*)d_out;
    // Opt-in for 48KB dynamic smem on top of static (attribute set is not a
    // stream op / allocation; graph-capture-safe, idempotent).
    cudaFuncSetAttribute(toptk_final, cudaFuncAttributeMaxDynamicSharedMemorySize,
                         CCAP * sizeof(float));
    toptk_stream<<<ROWS * SPLIT, NT1>>>(cam);
    toptk_final<<<ROWS, NT2, CCAP * sizeof(float)>>>(cam, out);
}